// round 15
// baseline (speedup 1.0000x reference)
#include <cuda_runtime.h>
#include <cstdint>

#define NODE_DIM 64
#define MSG_DIM  64
#define PROP_DIM 32
#define HIDDEN   128
#define T_DIM    8
#define S_DIM    16

#define MAX_V    10000
#define GO 8             // groups per CTA iteration = one full node
#define FSTR 72          // fp32 floats per A row in smem: conflict-free LDS.64
#define GROUP_FLOATS (S_DIM * FSTR)   // 1152
#define NODE_FLOATS (GO * GROUP_FLOATS)  // 9216

// Scratch: base[v][h] = h_t[v].Wh + theta[v].Wp + b1
__device__ float g_base[MAX_V * HIDDEN];

// pack two fp32 -> fp16x2 (lo = first arg), round-to-nearest-even
__device__ __forceinline__ uint32_t pack_h2(float lo, float hi) {
    uint32_t r;
    asm("cvt.rn.f16x2.f32 %0, %1, %2;" : "=r"(r) : "f"(hi), "f"(lo));
    return r;
}

#define MMA_F16(D, a0, a1, a2, a3, b0, b1)                                    \
    asm volatile(                                                             \
        "mma.sync.aligned.m16n8k16.row.col.f32.f16.f16.f32 "                  \
        "{%0,%1,%2,%3}, {%4,%5,%6,%7}, {%8,%9}, {%0,%1,%2,%3};"               \
        : "+f"(D[0]), "+f"(D[1]), "+f"(D[2]), "+f"(D[3])                      \
        : "r"(a0), "r"(a1), "r"(a2), "r"(a3), "r"(b0), "r"(b1))

__device__ __forceinline__ void cp_async16(uint32_t dst_smem, const void* src) {
    asm volatile("cp.async.cg.shared.global [%0], [%1], 16;" :: "r"(dst_smem), "l"(src));
}

// ---------------------------------------------------------------------------
// Kernel 1 (tensorized, verified R12): base[v][h] = b1 + [h_t|theta][v] @ W_sub
// ---------------------------------------------------------------------------
__global__ __launch_bounds__(128) void base_mma_kernel(
    const float* __restrict__ h_t,
    const float* __restrict__ theta,
    const float* __restrict__ W1,
    const float* __restrict__ b1,
    int V)
{
    __shared__ uint32_t Asm[32 * 52];     // 6656 B
    __shared__ uint32_t Bts[128 * 52];    // 26624 B

    const int tid   = threadIdx.x;
    const int lane  = tid & 31;
    const int w     = tid >> 5;
    const int qd    = lane & 3;
    const int gq    = lane >> 2;
    const int chalf = w & 1;
    const int pl    = w >> 1;
    const int wbase = chalf * 64;
    const int v0    = blockIdx.x * 32;

    #pragma unroll 8
    for (int dp = 0; dp < 48; ++dp) {
        const int d0 = 2 * dp, d1 = 2 * dp + 1;
        const int r0 = d0 + ((d0 >> 6) * 65);
        const int r1 = d1 + ((d1 >> 6) * 65);
        float w0 = __ldg(&W1[r0 * HIDDEN + tid]);
        float w1 = __ldg(&W1[r1 * HIDDEN + tid]);
        Bts[tid * 52 + dp] = pack_h2(w0, w1);
    }

    #pragma unroll
    for (int i = 0; i < 4; ++i) {
        const int c = tid + i * 128;
        const int n = c >> 4, f4 = c & 15;
        int v = v0 + n; if (v > V - 1) v = V - 1;
        float4 x = __ldg((const float4*)&h_t[(size_t)v * NODE_DIM + f4 * 4]);
        Asm[n * 52 + f4 * 2]     = pack_h2(x.x, x.y);
        Asm[n * 52 + f4 * 2 + 1] = pack_h2(x.z, x.w);
    }
    #pragma unroll
    for (int i = 0; i < 2; ++i) {
        const int c = tid + i * 128;
        const int n = c >> 3, f4 = c & 7;
        int v = v0 + n; if (v > V - 1) v = V - 1;
        float4 x = __ldg((const float4*)&theta[(size_t)v * PROP_DIM + f4 * 4]);
        Asm[n * 52 + 32 + f4 * 2]     = pack_h2(x.x, x.y);
        Asm[n * 52 + 32 + f4 * 2 + 1] = pack_h2(x.z, x.w);
    }
    __syncthreads();

    float acc[8][4];
    #pragma unroll
    for (int nb = 0; nb < 8; ++nb)
        #pragma unroll
        for (int i = 0; i < 4; ++i) acc[nb][i] = 0.f;

    const uint32_t* Arow = Asm + (pl * 16) * 52;
    #pragma unroll
    for (int kk = 0; kk < 6; ++kk) {
        const int ko = kk * 8 + qd;
        uint32_t a0 = Arow[gq * 52 + ko];
        uint32_t a1 = Arow[(gq + 8) * 52 + ko];
        uint32_t a2 = Arow[gq * 52 + ko + 4];
        uint32_t a3 = Arow[(gq + 8) * 52 + ko + 4];
        #pragma unroll
        for (int nb = 0; nb < 8; ++nb) {
            const uint32_t* Bc = Bts + (wbase + nb * 8 + gq) * 52 + ko;
            MMA_F16(acc[nb], a0, a1, a2, a3, Bc[0], Bc[4]);
        }
    }

    const int r_lo = v0 + pl * 16 + gq;
    const int r_hi = r_lo + 8;
    #pragma unroll
    for (int nb = 0; nb < 8; ++nb) {
        const int c0 = wbase + nb * 8 + qd * 2;
        float2 bv = __ldg((const float2*)&b1[c0]);
        if (r_lo < V) {
            float2 o; o.x = acc[nb][0] + bv.x; o.y = acc[nb][1] + bv.y;
            *(float2*)&g_base[(size_t)r_lo * HIDDEN + c0] = o;
        }
        if (r_hi < V) {
            float2 o; o.x = acc[nb][2] + bv.x; o.y = acc[nb][3] + bv.y;
            *(float2*)&g_base[(size_t)r_hi * HIDDEN + c0] = o;
        }
    }
}

// ---------------------------------------------------------------------------
// Kernel 2: octo-tile (GO=8 = one node / iteration), 256 threads, 2 CTAs/SM.
// Same 16 warps/SM as R12 but syncs/stage/store amortized over 8 groups.
// R12 epilogue structure (addsm precompute, acc=0) — R14 fold reverted.
//
// Dynamic smem layout (floats):
//   As[2][9216]  [0, 18432)
//   bsm[2][128]  [18432, 18688)
//   red[2][8][16][2]  512 floats  [18688, 19200)
//   taW[8][128]  [19200, 20224)
//   W2sm[128]    [20224, 20352)
//   addsm[8][128][20352, 21376)   -> 85504 B total
// ---------------------------------------------------------------------------
#define SM_AS    0
#define SM_BSM   18432
#define SM_RED   18688
#define SM_TAW   19200
#define SM_W2    20224
#define SM_ADD   20352
#define SM_BYTES (21376 * 4)

__device__ __forceinline__ void stage_node(
    float* Asb, float* bsb,
    const float* __restrict__ messages, int n, int tid)
{
    const float* msrc = messages + (size_t)n * (GO * S_DIM * MSG_DIM);
    #pragma unroll
    for (int i = 0; i < 8; ++i) {
        int c   = tid + i * 256;      // 16B chunk index, 0..2047
        int grp = c >> 8;
        int m   = c & 255;
        int row = m >> 4;
        int cc  = m & 15;
        uint32_t dst = (uint32_t)__cvta_generic_to_shared(
            Asb + grp * GROUP_FLOATS + row * FSTR + cc * 4);
        cp_async16(dst, msrc + c * 4);
    }
    if (tid < 32) {
        uint32_t dst = (uint32_t)__cvta_generic_to_shared(bsb + tid * 4);
        cp_async16(dst, g_base + (size_t)n * HIDDEN + tid * 4);
    }
}

__global__ __launch_bounds__(256, 2) void main_kernel(
    const float* __restrict__ messages,
    const float* __restrict__ tau_values,
    const float* __restrict__ W1,
    const float* __restrict__ W2,
    const float* __restrict__ b2,
    float* __restrict__ out,
    int V)
{
    extern __shared__ float sm[];
    float* As0   = sm + SM_AS;
    float* As1   = sm + SM_AS + NODE_FLOATS;
    float* bsm0  = sm + SM_BSM;
    float* bsm1  = sm + SM_BSM + HIDDEN;
    float* redp  = sm + SM_RED;                 // [buf][j][row][chalf]
    float* taW   = sm + SM_TAW;                 // [t][c]
    float* W2sm  = sm + SM_W2;
    float* addsm = sm + SM_ADD;                 // [j][c]

    const int tid   = threadIdx.x;
    const int lane  = tid & 31;
    const int w     = tid >> 5;          // 0..7
    const int qd    = lane & 3;
    const int gq    = lane >> 2;
    const int chalf = w & 1;             // column half
    const int pair  = w >> 1;            // 0..3; handles groups pair, pair+4
    const int wbase = chalf * 64;

    const int grid = gridDim.x;
    int n = blockIdx.x;                  // node index; grid clamped to V

    stage_node(As0, bsm0, messages, n, tid);
    asm volatile("cp.async.commit_group;");

    // --- Persistent B fragments (fp16x2): 8 n-blocks of this warp's half ---
    uint32_t bf[8][4][2];
    {
        const float* Wm = W1 + NODE_DIM * HIDDEN;
        #pragma unroll
        for (int nb = 0; nb < 8; ++nb) {
            const int col = wbase + nb * 8 + gq;
            #pragma unroll
            for (int kk = 0; kk < 4; ++kk) {
                const int kb = kk * 16 + 2 * qd;
                bf[nb][kk][0] = pack_h2(Wm[(kb)     * HIDDEN + col],
                                        Wm[(kb + 1) * HIDDEN + col]);
                bf[nb][kk][1] = pack_h2(Wm[(kb + 8) * HIDDEN + col],
                                        Wm[(kb + 9) * HIDDEN + col]);
            }
        }
    }

    // --- Epilogue constants ---
    if (tid < HIDDEN) {
        const float* Wt = W1 + (NODE_DIM + MSG_DIM) * HIDDEN;
        float wt = Wt[tid];
        #pragma unroll
        for (int t = 0; t < T_DIM; ++t)
            taW[t * HIDDEN + tid] = __ldg(&tau_values[t]) * wt;
        W2sm[tid] = W2[tid];
    }
    const float b2v = __ldg(&b2[0]);

    asm volatile("cp.async.wait_group 0;");
    __syncthreads();   // buf0 + taW/W2sm visible

    int cur = 0;
    for (;;) {
        const bool hasNext = (n + grid < V);

        if (hasNext) {
            stage_node(cur ? As0 : As1, cur ? bsm0 : bsm1,
                       messages, n + grid, tid);
            asm volatile("cp.async.commit_group;");
        }

        const float* Abuf = cur ? As1 : As0;
        const float* bcur = cur ? bsm1 : bsm0;
        float* redc = redp + cur * (GO * S_DIM * 2);

        // per-warp addsm: add[j][c] = base[c] + tau_j*Wt[c], own cols, 2 j's
        {
            const int col = wbase + lane * 2;
            float2 bv = *(const float2*)&bcur[col];
            #pragma unroll
            for (int jj = 0; jj < 2; ++jj) {
                const int j = pair + 4 * jj;     // t index == j (g0 = 8n)
                float2 tw = *(const float2*)&taW[j * HIDDEN + col];
                float2 ad;
                ad.x = bv.x + tw.x;
                ad.y = bv.y + tw.y;
                *(float2*)&addsm[j * HIDDEN + col] = ad;
            }
        }
        __syncwarp();

        #pragma unroll
        for (int jj = 0; jj < 2; ++jj) {
            const int j = pair + 4 * jj;
            const float* Ab = Abuf + j * GROUP_FLOATS;

            float acc[8][4];
            #pragma unroll
            for (int nb = 0; nb < 8; ++nb)
                #pragma unroll
                for (int i = 0; i < 4; ++i) acc[nb][i] = 0.f;

            #pragma unroll
            for (int kk = 0; kk < 4; ++kk) {
                const float* Ak = Ab + kk * 16 + 2 * qd;
                float2 v0 = *(const float2*)&Ak[gq * FSTR];
                float2 v1 = *(const float2*)&Ak[(gq + 8) * FSTR];
                float2 v2 = *(const float2*)&Ak[gq * FSTR + 8];
                float2 v3 = *(const float2*)&Ak[(gq + 8) * FSTR + 8];
                uint32_t a0 = pack_h2(v0.x, v0.y);
                uint32_t a1 = pack_h2(v1.x, v1.y);
                uint32_t a2 = pack_h2(v2.x, v2.y);
                uint32_t a3 = pack_h2(v3.x, v3.y);
                #pragma unroll
                for (int nb = 0; nb < 8; ++nb)
                    MMA_F16(acc[nb], a0, a1, a2, a3, bf[nb][kk][0], bf[nb][kk][1]);
            }

            // Lean epilogue (R12): add precomputed, relu, *W2; two chains
            const float* adj = addsm + j * HIDDEN;
            float pl0 = 0.f, pl1 = 0.f, ph0 = 0.f, ph1 = 0.f;
            #pragma unroll
            for (int nb = 0; nb < 8; ++nb) {
                const int c0 = wbase + nb * 8 + qd * 2;
                float2 ad = *(const float2*)&adj[c0];
                float2 w2 = *(const float2*)&W2sm[c0];
                if (nb & 1) {
                    pl1 = fmaf(fmaxf(acc[nb][0] + ad.x, 0.f), w2.x, pl1);
                    pl1 = fmaf(fmaxf(acc[nb][1] + ad.y, 0.f), w2.y, pl1);
                    ph1 = fmaf(fmaxf(acc[nb][2] + ad.x, 0.f), w2.x, ph1);
                    ph1 = fmaf(fmaxf(acc[nb][3] + ad.y, 0.f), w2.y, ph1);
                } else {
                    pl0 = fmaf(fmaxf(acc[nb][0] + ad.x, 0.f), w2.x, pl0);
                    pl0 = fmaf(fmaxf(acc[nb][1] + ad.y, 0.f), w2.y, pl0);
                    ph0 = fmaf(fmaxf(acc[nb][2] + ad.x, 0.f), w2.x, ph0);
                    ph0 = fmaf(fmaxf(acc[nb][3] + ad.y, 0.f), w2.y, ph0);
                }
            }
            float ps_lo = pl0 + pl1;
            float ps_hi = ph0 + ph1;
            ps_lo += __shfl_xor_sync(0xffffffffu, ps_lo, 1);
            ps_lo += __shfl_xor_sync(0xffffffffu, ps_lo, 2);
            ps_hi += __shfl_xor_sync(0xffffffffu, ps_hi, 1);
            ps_hi += __shfl_xor_sync(0xffffffffu, ps_hi, 2);
            if (qd == 0) {
                redc[(j * S_DIM + gq)     * 2 + chalf] = ps_lo;
                redc[(j * S_DIM + gq + 8) * 2 + chalf] = ps_hi;
            }
        }

        if (hasNext) asm volatile("cp.async.wait_group 0;");
        __syncthreads();   // next buf staged AND red[cur] ready

        // out-store: 128 outputs (one node), first 128 threads
        if (tid < GO * S_DIM) {
            const int j   = tid >> 4;
            const int row = tid & 15;
            out[((size_t)n * GO + j) * S_DIM + row] =
                redc[(j * S_DIM + row) * 2] + redc[(j * S_DIM + row) * 2 + 1] + b2v;
        }

        if (!hasNext) break;
        cur ^= 1;
        n += grid;
    }
}

// ---------------------------------------------------------------------------
extern "C" void kernel_launch(void* const* d_in, const int* in_sizes, int n_in,
                              void* d_out, int out_size)
{
    const float* h_t      = (const float*)d_in[0];
    const float* messages = (const float*)d_in[1];
    const float* tau      = (const float*)d_in[2];
    const float* theta    = (const float*)d_in[3];
    const float* W1       = (const float*)d_in[4];
    const float* b1       = (const float*)d_in[5];
    const float* W2       = (const float*)d_in[6];
    const float* b2       = (const float*)d_in[7];
    float* out = (float*)d_out;

    const int V = in_sizes[0] / NODE_DIM;

    base_mma_kernel<<<(V + 31) / 32, 128>>>(h_t, theta, W1, b1, V);

    cudaFuncSetAttribute(main_kernel,
                         cudaFuncAttributeMaxDynamicSharedMemorySize, SM_BYTES);

    int nb_occ = 0, nsm = 148;
    cudaOccupancyMaxActiveBlocksPerMultiprocessor(&nb_occ, main_kernel, 256, SM_BYTES);
    cudaDeviceGetAttribute(&nsm, cudaDevAttrMultiProcessorCount, 0);
    if (nb_occ < 1) nb_occ = 2;
    int grid = nb_occ * nsm;
    if (grid > V) grid = V;

    main_kernel<<<grid, 256, SM_BYTES>>>(messages, tau, W1, W2, b2, out, V);
}

// round 16
// speedup vs baseline: 1.0678x; 1.0678x over previous
#include <cuda_runtime.h>
#include <cstdint>

#define NODE_DIM 64
#define MSG_DIM  64
#define PROP_DIM 32
#define HIDDEN   128
#define T_DIM    8
#define S_DIM    16

#define MAX_V    10000
#define GQ 4             // groups per CTA iteration (quad) — proven optimum
#define FSTR 72          // fp32 floats per A row in smem: conflict-free LDS.64
#define GROUP_FLOATS (S_DIM * FSTR)   // 1152

// Scratch: base[v][h] = h_t[v].Wh + theta[v].Wp + b1
__device__ float g_base[MAX_V * HIDDEN];

// pack two fp32 -> fp16x2 (lo = first arg), round-to-nearest-even
__device__ __forceinline__ uint32_t pack_h2(float lo, float hi) {
    uint32_t r;
    asm("cvt.rn.f16x2.f32 %0, %1, %2;" : "=r"(r) : "f"(hi), "f"(lo));
    return r;
}

#define MMA_F16(D, a0, a1, a2, a3, b0, b1)                                    \
    asm volatile(                                                             \
        "mma.sync.aligned.m16n8k16.row.col.f32.f16.f16.f32 "                  \
        "{%0,%1,%2,%3}, {%4,%5,%6,%7}, {%8,%9}, {%0,%1,%2,%3};"               \
        : "+f"(D[0]), "+f"(D[1]), "+f"(D[2]), "+f"(D[3])                      \
        : "r"(a0), "r"(a1), "r"(a2), "r"(a3), "r"(b0), "r"(b1))

__device__ __forceinline__ void cp_async16(uint32_t dst_smem, const void* src) {
    asm volatile("cp.async.cg.shared.global [%0], [%1], 16;" :: "r"(dst_smem), "l"(src));
}

// ---------------------------------------------------------------------------
// Kernel 1 (tensorized, verified R12): base[v][h] = b1 + [h_t|theta][v] @ W_sub
// ---------------------------------------------------------------------------
__global__ __launch_bounds__(128) void base_mma_kernel(
    const float* __restrict__ h_t,
    const float* __restrict__ theta,
    const float* __restrict__ W1,
    const float* __restrict__ b1,
    int V)
{
    __shared__ uint32_t Asm[32 * 52];     // 6656 B
    __shared__ uint32_t Bts[128 * 52];    // 26624 B

    const int tid   = threadIdx.x;
    const int lane  = tid & 31;
    const int w     = tid >> 5;
    const int qd    = lane & 3;
    const int gq    = lane >> 2;
    const int chalf = w & 1;
    const int pl    = w >> 1;
    const int wbase = chalf * 64;
    const int v0    = blockIdx.x * 32;

    #pragma unroll 8
    for (int dp = 0; dp < 48; ++dp) {
        const int d0 = 2 * dp, d1 = 2 * dp + 1;
        const int r0 = d0 + ((d0 >> 6) * 65);
        const int r1 = d1 + ((d1 >> 6) * 65);
        float w0 = __ldg(&W1[r0 * HIDDEN + tid]);
        float w1 = __ldg(&W1[r1 * HIDDEN + tid]);
        Bts[tid * 52 + dp] = pack_h2(w0, w1);
    }

    #pragma unroll
    for (int i = 0; i < 4; ++i) {
        const int c = tid + i * 128;
        const int n = c >> 4, f4 = c & 15;
        int v = v0 + n; if (v > V - 1) v = V - 1;
        float4 x = __ldg((const float4*)&h_t[(size_t)v * NODE_DIM + f4 * 4]);
        Asm[n * 52 + f4 * 2]     = pack_h2(x.x, x.y);
        Asm[n * 52 + f4 * 2 + 1] = pack_h2(x.z, x.w);
    }
    #pragma unroll
    for (int i = 0; i < 2; ++i) {
        const int c = tid + i * 128;
        const int n = c >> 3, f4 = c & 7;
        int v = v0 + n; if (v > V - 1) v = V - 1;
        float4 x = __ldg((const float4*)&theta[(size_t)v * PROP_DIM + f4 * 4]);
        Asm[n * 52 + 32 + f4 * 2]     = pack_h2(x.x, x.y);
        Asm[n * 52 + 32 + f4 * 2 + 1] = pack_h2(x.z, x.w);
    }
    __syncthreads();

    float acc[8][4];
    #pragma unroll
    for (int nb = 0; nb < 8; ++nb)
        #pragma unroll
        for (int i = 0; i < 4; ++i) acc[nb][i] = 0.f;

    const uint32_t* Arow = Asm + (pl * 16) * 52;
    #pragma unroll
    for (int kk = 0; kk < 6; ++kk) {
        const int ko = kk * 8 + qd;
        uint32_t a0 = Arow[gq * 52 + ko];
        uint32_t a1 = Arow[(gq + 8) * 52 + ko];
        uint32_t a2 = Arow[gq * 52 + ko + 4];
        uint32_t a3 = Arow[(gq + 8) * 52 + ko + 4];
        #pragma unroll
        for (int nb = 0; nb < 8; ++nb) {
            const uint32_t* Bc = Bts + (wbase + nb * 8 + gq) * 52 + ko;
            MMA_F16(acc[nb], a0, a1, a2, a3, Bc[0], Bc[4]);
        }
    }

    const int r_lo = v0 + pl * 16 + gq;
    const int r_hi = r_lo + 8;
    #pragma unroll
    for (int nb = 0; nb < 8; ++nb) {
        const int c0 = wbase + nb * 8 + qd * 2;
        float2 bv = __ldg((const float2*)&b1[c0]);
        if (r_lo < V) {
            float2 o; o.x = acc[nb][0] + bv.x; o.y = acc[nb][1] + bv.y;
            *(float2*)&g_base[(size_t)r_lo * HIDDEN + c0] = o;
        }
        if (r_hi < V) {
            float2 o; o.x = acc[nb][2] + bv.x; o.y = acc[nb][3] + bv.y;
            *(float2*)&g_base[(size_t)r_hi * HIDDEN + c0] = o;
        }
    }
}

// ---------------------------------------------------------------------------
// Kernel 2: R12 quad-tile structure + double-buffered A-fragment pipeline:
// loads for kk+2 issue before the MMAs of kk, hiding LDS latency.
// ---------------------------------------------------------------------------

__device__ __forceinline__ void stage_quad(
    float* Asb, float* bsb,
    const float* __restrict__ messages, int q, int tid)
{
    const float* msrc = messages + (size_t)q * (GQ * S_DIM * MSG_DIM);
    #pragma unroll
    for (int i = 0; i < 8; ++i) {
        int c   = tid + i * 128;      // 16B chunk index, 0..1023
        int grp = c >> 8;
        int m   = c & 255;
        int row = m >> 4;
        int cc  = m & 15;
        uint32_t dst = (uint32_t)__cvta_generic_to_shared(
            Asb + grp * GROUP_FLOATS + row * FSTR + cc * 4);
        cp_async16(dst, msrc + c * 4);
    }
    if (tid < 32) {
        int v = q >> 1;   // quad q -> node q/2
        uint32_t dst = (uint32_t)__cvta_generic_to_shared(bsb + tid * 4);
        cp_async16(dst, g_base + (size_t)v * HIDDEN + tid * 4);
    }
}

// load + pack one kk-step's A fragments into a 4-reg bank
__device__ __forceinline__ void loadpack_A(
    uint32_t* A, const float* Ab, int kk, int qd, int gq)
{
    const float* Ak = Ab + kk * 16 + 2 * qd;
    float2 v0 = *(const float2*)&Ak[gq * FSTR];
    float2 v1 = *(const float2*)&Ak[(gq + 8) * FSTR];
    float2 v2 = *(const float2*)&Ak[gq * FSTR + 8];
    float2 v3 = *(const float2*)&Ak[(gq + 8) * FSTR + 8];
    A[0] = pack_h2(v0.x, v0.y);
    A[1] = pack_h2(v1.x, v1.y);
    A[2] = pack_h2(v2.x, v2.y);
    A[3] = pack_h2(v3.x, v3.y);
}

__global__ __launch_bounds__(128, 4) void main_kernel(
    const float* __restrict__ messages,
    const float* __restrict__ tau_values,
    const float* __restrict__ W1,
    const float* __restrict__ W2,
    const float* __restrict__ b2,
    float* __restrict__ out,
    int nGroups, int nQuads)
{
    __shared__ float As[2][GQ * GROUP_FLOATS];       // 36864 B
    __shared__ float bsm[2][HIDDEN];                 // 1024 B
    __shared__ float red[2][GQ][S_DIM][2];           // 1024 B
    __shared__ float taW[T_DIM][HIDDEN];             // 4096 B
    __shared__ float W2sm[HIDDEN];                   // 512 B
    __shared__ float addsm[GQ][HIDDEN];              // 2048 B

    const int tid   = threadIdx.x;
    const int lane  = tid & 31;
    const int w     = tid >> 5;
    const int qd    = lane & 3;
    const int gq    = lane >> 2;
    const int chalf = w & 1;
    const int jband = w >> 1;
    const int wbase = chalf * 64;

    const int grid = gridDim.x;
    int q = blockIdx.x;

    stage_quad(As[0], bsm[0], messages, q, tid);
    asm volatile("cp.async.commit_group;");

    // --- Persistent B fragments (fp16x2): 8 n-blocks of this warp's half ---
    uint32_t bf[8][4][2];
    {
        const float* Wm = W1 + NODE_DIM * HIDDEN;
        #pragma unroll
        for (int nb = 0; nb < 8; ++nb) {
            const int col = wbase + nb * 8 + gq;
            #pragma unroll
            for (int kk = 0; kk < 4; ++kk) {
                const int kb = kk * 16 + 2 * qd;
                bf[nb][kk][0] = pack_h2(Wm[(kb)     * HIDDEN + col],
                                        Wm[(kb + 1) * HIDDEN + col]);
                bf[nb][kk][1] = pack_h2(Wm[(kb + 8) * HIDDEN + col],
                                        Wm[(kb + 9) * HIDDEN + col]);
            }
        }
    }

    // --- Epilogue constants ---
    {
        const float* Wt = W1 + (NODE_DIM + MSG_DIM) * HIDDEN;
        float wt = Wt[tid];
        #pragma unroll
        for (int t = 0; t < T_DIM; ++t)
            taW[t][tid] = __ldg(&tau_values[t]) * wt;
        W2sm[tid] = W2[tid];
    }
    const float b2v = __ldg(&b2[0]);

    asm volatile("cp.async.wait_group 0;");
    __syncthreads();

    int cur = 0;
    for (;;) {
        const bool hasNext = (q + grid < nQuads);

        if (hasNext) {
            stage_quad(As[cur ^ 1], bsm[cur ^ 1], messages, q + grid, tid);
            asm volatile("cp.async.commit_group;");
        }

        const int g0 = q * GQ;
        const int t0 = g0 & (T_DIM - 1);

        // per-warp addsm: add[j][c] = base[c] + tau*Wt[c] for own cols
        {
            const int col = wbase + lane * 2;
            float2 bv = *(const float2*)&bsm[cur][col];
            #pragma unroll
            for (int jj = 0; jj < 2; ++jj) {
                const int j = jband + 2 * jj;
                float2 tw = *(const float2*)&taW[t0 + j][col];
                float2 ad;
                ad.x = bv.x + tw.x;
                ad.y = bv.y + tw.y;
                *(float2*)&addsm[j][col] = ad;
            }
        }
        __syncwarp();

        #pragma unroll
        for (int jj = 0; jj < 2; ++jj) {
            const int j = jband + 2 * jj;
            const float* Ab = &As[cur][j * GROUP_FLOATS];

            float acc[8][4];
            #pragma unroll
            for (int nb = 0; nb < 8; ++nb)
                #pragma unroll
                for (int i = 0; i < 4; ++i) acc[nb][i] = 0.f;

            // Double-buffered A-fragment pipeline: kk+2 loads issue before
            // kk's MMAs retire (independent), hiding LDS latency.
            uint32_t A0[4], A1[4];
            loadpack_A(A0, Ab, 0, qd, gq);
            loadpack_A(A1, Ab, 1, qd, gq);

            #pragma unroll
            for (int nb = 0; nb < 8; ++nb)
                MMA_F16(acc[nb], A0[0], A0[1], A0[2], A0[3], bf[nb][0][0], bf[nb][0][1]);
            loadpack_A(A0, Ab, 2, qd, gq);

            #pragma unroll
            for (int nb = 0; nb < 8; ++nb)
                MMA_F16(acc[nb], A1[0], A1[1], A1[2], A1[3], bf[nb][1][0], bf[nb][1][1]);
            loadpack_A(A1, Ab, 3, qd, gq);

            #pragma unroll
            for (int nb = 0; nb < 8; ++nb)
                MMA_F16(acc[nb], A0[0], A0[1], A0[2], A0[3], bf[nb][2][0], bf[nb][2][1]);

            #pragma unroll
            for (int nb = 0; nb < 8; ++nb)
                MMA_F16(acc[nb], A1[0], A1[1], A1[2], A1[3], bf[nb][3][0], bf[nb][3][1]);

            // Lean epilogue: add precomputed, relu, *W2; two FMA chains
            const float* adj = addsm[j];
            float pl0 = 0.f, pl1 = 0.f, ph0 = 0.f, ph1 = 0.f;
            #pragma unroll
            for (int nb = 0; nb < 8; ++nb) {
                const int c0 = wbase + nb * 8 + qd * 2;
                float2 ad = *(const float2*)&adj[c0];
                float2 w2 = *(const float2*)&W2sm[c0];
                if (nb & 1) {
                    pl1 = fmaf(fmaxf(acc[nb][0] + ad.x, 0.f), w2.x, pl1);
                    pl1 = fmaf(fmaxf(acc[nb][1] + ad.y, 0.f), w2.y, pl1);
                    ph1 = fmaf(fmaxf(acc[nb][2] + ad.x, 0.f), w2.x, ph1);
                    ph1 = fmaf(fmaxf(acc[nb][3] + ad.y, 0.f), w2.y, ph1);
                } else {
                    pl0 = fmaf(fmaxf(acc[nb][0] + ad.x, 0.f), w2.x, pl0);
                    pl0 = fmaf(fmaxf(acc[nb][1] + ad.y, 0.f), w2.y, pl0);
                    ph0 = fmaf(fmaxf(acc[nb][2] + ad.x, 0.f), w2.x, ph0);
                    ph0 = fmaf(fmaxf(acc[nb][3] + ad.y, 0.f), w2.y, ph0);
                }
            }
            float ps_lo = pl0 + pl1;
            float ps_hi = ph0 + ph1;
            ps_lo += __shfl_xor_sync(0xffffffffu, ps_lo, 1);
            ps_lo += __shfl_xor_sync(0xffffffffu, ps_lo, 2);
            ps_hi += __shfl_xor_sync(0xffffffffu, ps_hi, 1);
            ps_hi += __shfl_xor_sync(0xffffffffu, ps_hi, 2);
            if (qd == 0) {
                red[cur][j][gq][chalf]     = ps_lo;
                red[cur][j][gq + 8][chalf] = ps_hi;
            }
        }

        if (hasNext) asm volatile("cp.async.wait_group 0;");
        __syncthreads();   // buf[cur^1] staged AND red[cur] ready

        if (tid < GQ * S_DIM) {
            const int j   = tid >> 4;
            const int row = tid & 15;
            const int g   = g0 + j;
            if (g < nGroups)
                out[(size_t)g * S_DIM + row] =
                    red[cur][j][row][0] + red[cur][j][row][1] + b2v;
        }

        if (!hasNext) break;
        cur ^= 1;
        q += grid;
    }
}

// ---------------------------------------------------------------------------
extern "C" void kernel_launch(void* const* d_in, const int* in_sizes, int n_in,
                              void* d_out, int out_size)
{
    const float* h_t      = (const float*)d_in[0];
    const float* messages = (const float*)d_in[1];
    const float* tau      = (const float*)d_in[2];
    const float* theta    = (const float*)d_in[3];
    const float* W1       = (const float*)d_in[4];
    const float* b1       = (const float*)d_in[5];
    const float* W2       = (const float*)d_in[6];
    const float* b2       = (const float*)d_in[7];
    float* out = (float*)d_out;

    const int V = in_sizes[0] / NODE_DIM;
    const int nGroups = V * T_DIM;
    const int nQuads  = nGroups / GQ;

    base_mma_kernel<<<(V + 31) / 32, 128>>>(h_t, theta, W1, b1, V);

    int nb_occ = 0, nsm = 148;
    cudaOccupancyMaxActiveBlocksPerMultiprocessor(&nb_occ, main_kernel, 128, 0);
    cudaDeviceGetAttribute(&nsm, cudaDevAttrMultiProcessorCount, 0);
    if (nb_occ < 1) nb_occ = 4;
    int grid = nb_occ * nsm;
    if (grid > nQuads) grid = nQuads;

    main_kernel<<<grid, 128>>>(messages, tau, W1, W2, b2, out, nGroups, nQuads);
}

// round 17
// speedup vs baseline: 1.0710x; 1.0030x over previous
#include <cuda_runtime.h>
#include <cstdint>

#define NODE_DIM 64
#define MSG_DIM  64
#define PROP_DIM 32
#define HIDDEN   128
#define T_DIM    8
#define S_DIM    16

#define MAX_V    10000
#define GQ 4             // groups per CTA iteration (quad) — proven optimum
#define FSTR 72          // fp32 floats per A row in smem: conflict-free LDS.64
#define GROUP_FLOATS (S_DIM * FSTR)   // 1152

// Scratch: base[v][h] = h_t[v].Wh + theta[v].Wp + b1
__device__ float g_base[MAX_V * HIDDEN];

// pack two fp32 -> fp16x2 (lo = first arg), round-to-nearest-even
__device__ __forceinline__ uint32_t pack_h2(float lo, float hi) {
    uint32_t r;
    asm("cvt.rn.f16x2.f32 %0, %1, %2;" : "=r"(r) : "f"(hi), "f"(lo));
    return r;
}

#define MMA_F16(D, a0, a1, a2, a3, b0, b1)                                    \
    asm volatile(                                                             \
        "mma.sync.aligned.m16n8k16.row.col.f32.f16.f16.f32 "                  \
        "{%0,%1,%2,%3}, {%4,%5,%6,%7}, {%8,%9}, {%0,%1,%2,%3};"               \
        : "+f"(D[0]), "+f"(D[1]), "+f"(D[2]), "+f"(D[3])                      \
        : "r"(a0), "r"(a1), "r"(a2), "r"(a3), "r"(b0), "r"(b1))

__device__ __forceinline__ void cp_async16(uint32_t dst_smem, const void* src) {
    asm volatile("cp.async.cg.shared.global [%0], [%1], 16;" :: "r"(dst_smem), "l"(src));
}

// ---------------------------------------------------------------------------
// Kernel 1 (tensorized): base[v][h] = b1 + [h_t|theta][v] @ W_sub
// 2 node-tiles (64 nodes) per CTA: W staged ONCE, amortized over both tiles.
// W1 rows: Wh = 0..63, Wm = 64..127, Wt = 128, Wp = 129..160
// ---------------------------------------------------------------------------
__global__ __launch_bounds__(128) void base_mma_kernel(
    const float* __restrict__ h_t,
    const float* __restrict__ theta,
    const float* __restrict__ W1,
    const float* __restrict__ b1,
    int V)
{
    __shared__ uint32_t Asm[32 * 52];     // 6656 B
    __shared__ uint32_t Bts[128 * 52];    // 26624 B

    const int tid   = threadIdx.x;
    const int lane  = tid & 31;
    const int w     = tid >> 5;
    const int qd    = lane & 3;
    const int gq    = lane >> 2;
    const int chalf = w & 1;
    const int pl    = w >> 1;
    const int wbase = chalf * 64;

    // --- Stage B transposed (once per CTA) ---
    #pragma unroll 8
    for (int dp = 0; dp < 48; ++dp) {
        const int d0 = 2 * dp, d1 = 2 * dp + 1;
        const int r0 = d0 + ((d0 >> 6) * 65);
        const int r1 = d1 + ((d1 >> 6) * 65);
        float w0 = __ldg(&W1[r0 * HIDDEN + tid]);
        float w1 = __ldg(&W1[r1 * HIDDEN + tid]);
        Bts[tid * 52 + dp] = pack_h2(w0, w1);
    }

    #pragma unroll
    for (int tile = 0; tile < 2; ++tile) {
        const int v0 = (blockIdx.x * 2 + tile) * 32;
        if (v0 >= V) break;

        if (tile) __syncthreads();   // prior MMA reads of Asm complete

        // --- Stage A: rows = nodes, cols 0..63 = h_t, 64..95 = theta ---
        #pragma unroll
        for (int i = 0; i < 4; ++i) {
            const int c = tid + i * 128;
            const int n = c >> 4, f4 = c & 15;
            int v = v0 + n; if (v > V - 1) v = V - 1;
            float4 x = __ldg((const float4*)&h_t[(size_t)v * NODE_DIM + f4 * 4]);
            Asm[n * 52 + f4 * 2]     = pack_h2(x.x, x.y);
            Asm[n * 52 + f4 * 2 + 1] = pack_h2(x.z, x.w);
        }
        #pragma unroll
        for (int i = 0; i < 2; ++i) {
            const int c = tid + i * 128;
            const int n = c >> 3, f4 = c & 7;
            int v = v0 + n; if (v > V - 1) v = V - 1;
            float4 x = __ldg((const float4*)&theta[(size_t)v * PROP_DIM + f4 * 4]);
            Asm[n * 52 + 32 + f4 * 2]     = pack_h2(x.x, x.y);
            Asm[n * 52 + 32 + f4 * 2 + 1] = pack_h2(x.z, x.w);
        }
        __syncthreads();

        float acc[8][4];
        #pragma unroll
        for (int nb = 0; nb < 8; ++nb)
            #pragma unroll
            for (int i = 0; i < 4; ++i) acc[nb][i] = 0.f;

        const uint32_t* Arow = Asm + (pl * 16) * 52;
        #pragma unroll
        for (int kk = 0; kk < 6; ++kk) {
            const int ko = kk * 8 + qd;
            uint32_t a0 = Arow[gq * 52 + ko];
            uint32_t a1 = Arow[(gq + 8) * 52 + ko];
            uint32_t a2 = Arow[gq * 52 + ko + 4];
            uint32_t a3 = Arow[(gq + 8) * 52 + ko + 4];
            #pragma unroll
            for (int nb = 0; nb < 8; ++nb) {
                const uint32_t* Bc = Bts + (wbase + nb * 8 + gq) * 52 + ko;
                MMA_F16(acc[nb], a0, a1, a2, a3, Bc[0], Bc[4]);
            }
        }

        const int r_lo = v0 + pl * 16 + gq;
        const int r_hi = r_lo + 8;
        #pragma unroll
        for (int nb = 0; nb < 8; ++nb) {
            const int c0 = wbase + nb * 8 + qd * 2;
            float2 bv = __ldg((const float2*)&b1[c0]);
            if (r_lo < V) {
                float2 o; o.x = acc[nb][0] + bv.x; o.y = acc[nb][1] + bv.y;
                *(float2*)&g_base[(size_t)r_lo * HIDDEN + c0] = o;
            }
            if (r_hi < V) {
                float2 o; o.x = acc[nb][2] + bv.x; o.y = acc[nb][3] + bv.y;
                *(float2*)&g_base[(size_t)r_hi * HIDDEN + c0] = o;
            }
        }
    }
}

// ---------------------------------------------------------------------------
// Kernel 2: R12 quad-tile structure with SPLIT staging — half the cp.async
// burst at loop top, half between the two group-MMA blocks. Same bytes,
// smaller L1tex queue bursts, decorrelated across resident CTAs.
// ---------------------------------------------------------------------------

__device__ __forceinline__ void stage_half(
    float* Asb, const float* __restrict__ messages, int q, int tid, int h)
{
    const float* msrc = messages + (size_t)q * (GQ * S_DIM * MSG_DIM);
    #pragma unroll
    for (int i = h * 4; i < h * 4 + 4; ++i) {
        int c   = tid + i * 128;      // 16B chunk index, 0..1023
        int grp = c >> 8;
        int m   = c & 255;
        int row = m >> 4;
        int cc  = m & 15;
        uint32_t dst = (uint32_t)__cvta_generic_to_shared(
            Asb + grp * GROUP_FLOATS + row * FSTR + cc * 4);
        cp_async16(dst, msrc + c * 4);
    }
}

__device__ __forceinline__ void stage_base(
    float* bsb, int q, int tid)
{
    if (tid < 32) {
        int v = q >> 1;   // quad q -> node q/2
        uint32_t dst = (uint32_t)__cvta_generic_to_shared(bsb + tid * 4);
        cp_async16(dst, g_base + (size_t)v * HIDDEN + tid * 4);
    }
}

__global__ __launch_bounds__(128, 4) void main_kernel(
    const float* __restrict__ messages,
    const float* __restrict__ tau_values,
    const float* __restrict__ W1,
    const float* __restrict__ W2,
    const float* __restrict__ b2,
    float* __restrict__ out,
    int nGroups, int nQuads)
{
    __shared__ float As[2][GQ * GROUP_FLOATS];       // 36864 B
    __shared__ float bsm[2][HIDDEN];                 // 1024 B
    __shared__ float red[2][GQ][S_DIM][2];           // 1024 B
    __shared__ float taW[T_DIM][HIDDEN];             // 4096 B
    __shared__ float W2sm[HIDDEN];                   // 512 B
    __shared__ float addsm[GQ][HIDDEN];              // 2048 B

    const int tid   = threadIdx.x;
    const int lane  = tid & 31;
    const int w     = tid >> 5;
    const int qd    = lane & 3;
    const int gq    = lane >> 2;
    const int chalf = w & 1;
    const int jband = w >> 1;
    const int wbase = chalf * 64;

    const int grid = gridDim.x;
    int q = blockIdx.x;

    stage_half(As[0], messages, q, tid, 0);
    stage_half(As[0], messages, q, tid, 1);
    stage_base(bsm[0], q, tid);
    asm volatile("cp.async.commit_group;");

    // --- Persistent B fragments (fp16x2): 8 n-blocks of this warp's half ---
    uint32_t bf[8][4][2];
    {
        const float* Wm = W1 + NODE_DIM * HIDDEN;
        #pragma unroll
        for (int nb = 0; nb < 8; ++nb) {
            const int col = wbase + nb * 8 + gq;
            #pragma unroll
            for (int kk = 0; kk < 4; ++kk) {
                const int kb = kk * 16 + 2 * qd;
                bf[nb][kk][0] = pack_h2(Wm[(kb)     * HIDDEN + col],
                                        Wm[(kb + 1) * HIDDEN + col]);
                bf[nb][kk][1] = pack_h2(Wm[(kb + 8) * HIDDEN + col],
                                        Wm[(kb + 9) * HIDDEN + col]);
            }
        }
    }

    // --- Epilogue constants ---
    {
        const float* Wt = W1 + (NODE_DIM + MSG_DIM) * HIDDEN;
        float wt = Wt[tid];
        #pragma unroll
        for (int t = 0; t < T_DIM; ++t)
            taW[t][tid] = __ldg(&tau_values[t]) * wt;
        W2sm[tid] = W2[tid];
    }
    const float b2v = __ldg(&b2[0]);

    asm volatile("cp.async.wait_group 0;");
    __syncthreads();

    int cur = 0;
    for (;;) {
        const bool hasNext = (q + grid < nQuads);
        const int qn = q + grid;

        // (1a) first half of next-quad staging (small burst)
        if (hasNext) stage_half(As[cur ^ 1], messages, qn, tid, 0);

        const int g0 = q * GQ;
        const int t0 = g0 & (T_DIM - 1);

        // per-warp addsm: add[j][c] = base[c] + tau*Wt[c] for own cols
        {
            const int col = wbase + lane * 2;
            float2 bv = *(const float2*)&bsm[cur][col];
            #pragma unroll
            for (int jj = 0; jj < 2; ++jj) {
                const int j = jband + 2 * jj;
                float2 tw = *(const float2*)&taW[t0 + j][col];
                float2 ad;
                ad.x = bv.x + tw.x;
                ad.y = bv.y + tw.y;
                *(float2*)&addsm[j][col] = ad;
            }
        }
        __syncwarp();

        #pragma unroll
        for (int jj = 0; jj < 2; ++jj) {
            const int j = jband + 2 * jj;
            const float* Ab = &As[cur][j * GROUP_FLOATS];

            float acc[8][4];
            #pragma unroll
            for (int nb = 0; nb < 8; ++nb)
                #pragma unroll
                for (int i = 0; i < 4; ++i) acc[nb][i] = 0.f;

            #pragma unroll
            for (int kk = 0; kk < 4; ++kk) {
                const float* Ak = Ab + kk * 16 + 2 * qd;
                float2 v0 = *(const float2*)&Ak[gq * FSTR];
                float2 v1 = *(const float2*)&Ak[(gq + 8) * FSTR];
                float2 v2 = *(const float2*)&Ak[gq * FSTR + 8];
                float2 v3 = *(const float2*)&Ak[(gq + 8) * FSTR + 8];
                uint32_t a0 = pack_h2(v0.x, v0.y);
                uint32_t a1 = pack_h2(v1.x, v1.y);
                uint32_t a2 = pack_h2(v2.x, v2.y);
                uint32_t a3 = pack_h2(v3.x, v3.y);
                #pragma unroll
                for (int nb = 0; nb < 8; ++nb)
                    MMA_F16(acc[nb], a0, a1, a2, a3, bf[nb][kk][0], bf[nb][kk][1]);
            }

            // Lean epilogue: add precomputed, relu, *W2; two FMA chains
            const float* adj = addsm[j];
            float pl0 = 0.f, pl1 = 0.f, ph0 = 0.f, ph1 = 0.f;
            #pragma unroll
            for (int nb = 0; nb < 8; ++nb) {
                const int c0 = wbase + nb * 8 + qd * 2;
                float2 ad = *(const float2*)&adj[c0];
                float2 w2 = *(const float2*)&W2sm[c0];
                if (nb & 1) {
                    pl1 = fmaf(fmaxf(acc[nb][0] + ad.x, 0.f), w2.x, pl1);
                    pl1 = fmaf(fmaxf(acc[nb][1] + ad.y, 0.f), w2.y, pl1);
                    ph1 = fmaf(fmaxf(acc[nb][2] + ad.x, 0.f), w2.x, ph1);
                    ph1 = fmaf(fmaxf(acc[nb][3] + ad.y, 0.f), w2.y, ph1);
                } else {
                    pl0 = fmaf(fmaxf(acc[nb][0] + ad.x, 0.f), w2.x, pl0);
                    pl0 = fmaf(fmaxf(acc[nb][1] + ad.y, 0.f), w2.y, pl0);
                    ph0 = fmaf(fmaxf(acc[nb][2] + ad.x, 0.f), w2.x, ph0);
                    ph0 = fmaf(fmaxf(acc[nb][3] + ad.y, 0.f), w2.y, ph0);
                }
            }
            float ps_lo = pl0 + pl1;
            float ps_hi = ph0 + ph1;
            ps_lo += __shfl_xor_sync(0xffffffffu, ps_lo, 1);
            ps_lo += __shfl_xor_sync(0xffffffffu, ps_lo, 2);
            ps_hi += __shfl_xor_sync(0xffffffffu, ps_hi, 1);
            ps_hi += __shfl_xor_sync(0xffffffffu, ps_hi, 2);
            if (qd == 0) {
                red[cur][j][gq][chalf]     = ps_lo;
                red[cur][j][gq + 8][chalf] = ps_hi;
            }

            // (1b) second half of next-quad staging between the two groups
            if (jj == 0 && hasNext) {
                stage_half(As[cur ^ 1], messages, qn, tid, 1);
                stage_base(bsm[cur ^ 1], qn, tid);
                asm volatile("cp.async.commit_group;");
            }
        }

        if (hasNext) asm volatile("cp.async.wait_group 0;");
        __syncthreads();   // buf[cur^1] staged AND red[cur] ready

        if (tid < GQ * S_DIM) {
            const int j   = tid >> 4;
            const int row = tid & 15;
            const int g   = g0 + j;
            if (g < nGroups)
                out[(size_t)g * S_DIM + row] =
                    red[cur][j][row][0] + red[cur][j][row][1] + b2v;
        }

        if (!hasNext) break;
        cur ^= 1;
        q = qn;
    }
}

// ---------------------------------------------------------------------------
extern "C" void kernel_launch(void* const* d_in, const int* in_sizes, int n_in,
                              void* d_out, int out_size)
{
    const float* h_t      = (const float*)d_in[0];
    const float* messages = (const float*)d_in[1];
    const float* tau      = (const float*)d_in[2];
    const float* theta    = (const float*)d_in[3];
    const float* W1       = (const float*)d_in[4];
    const float* b1       = (const float*)d_in[5];
    const float* W2       = (const float*)d_in[6];
    const float* b2       = (const float*)d_in[7];
    float* out = (float*)d_out;

    const int V = in_sizes[0] / NODE_DIM;
    const int nGroups = V * T_DIM;
    const int nQuads  = nGroups / GQ;

    base_mma_kernel<<<(V + 63) / 64, 128>>>(h_t, theta, W1, b1, V);

    int nb_occ = 0, nsm = 148;
    cudaOccupancyMaxActiveBlocksPerMultiprocessor(&nb_occ, main_kernel, 128, 0);
    cudaDeviceGetAttribute(&nsm, cudaDevAttrMultiProcessorCount, 0);
    if (nb_occ < 1) nb_occ = 4;
    int grid = nb_occ * nsm;
    if (grid > nQuads) grid = nQuads;

    main_kernel<<<grid, 128>>>(messages, tau, W1, W2, b2, out, nGroups, nQuads);
}